// round 5
// baseline (speedup 1.0000x reference)
#include <cuda_runtime.h>
#include <math.h>

#define NTOK   8192
#define NPAIR  (NTOK * 2)
#define NE     64
#define TPB    16
#define MAXCHUNK (NPAIR / TPB + NE)   // 1088

// ---- scratch (device globals; no allocs allowed) ----
__device__ float g_h[(size_t)NTOK * 4096];        // 134 MB
__device__ float g_yup[(size_t)NPAIR * 4096];     // 268 MB
__device__ float g_ydown[(size_t)NPAIR * 1024];   // 67 MB
__device__ float g_logits[(size_t)NTOK * NE];     // 2 MB
__device__ float g_logits2[(size_t)NTOK * NE];    // 2 MB (K-split partial)
__device__ float g_prob[NPAIR];
__device__ int   g_cnt[NE];
__device__ int   g_list[NE * NPAIR];              // 4 MB
__device__ int2  g_chunk[MAXCHUNK];
__device__ int   g_nchunks;

typedef unsigned long long ull;

__device__ __forceinline__ float gelu_erf(float v) { return v * normcdff(v); }

// ---- packed f32x2 helpers (sm_103a FFMA2; PTX-only, ptxas won't auto-fuse) ----
__device__ __forceinline__ ull pack2(float lo, float hi) {
    ull r;
    asm("mov.b64 %0, {%1, %2};" : "=l"(r) : "f"(lo), "f"(hi));
    return r;
}
__device__ __forceinline__ float2 unpack2(ull v) {
    float lo, hi;
    asm("mov.b64 {%0, %1}, %2;" : "=f"(lo), "=f"(hi) : "l"(v));
    return make_float2(lo, hi);
}
__device__ __forceinline__ ull ffma2(ull a, ull b, ull c) {
    ull d;
    asm("fma.rn.f32x2 %0, %1, %2, %3;" : "=l"(d) : "l"(a), "l"(b), "l"(c));
    return d;
}

// ---------------------------------------------------------------------------
// Router GEMM: logits[M,64] = X[M,Ktot] * W[64,Ktot]^T, 64-token tiles.
// NPARTS=2: grid doubles; upper half computes k in [KLEN,2*KLEN) -> out2.
// Inner loop: 2 distinct scalar LDS + 2 uniform LDS.128 + 8 FFMA2 per k.
// ---------------------------------------------------------------------------
template<int KLEN, int NPARTS>
__global__ __launch_bounds__(256) void router_gemm(
    const float* __restrict__ X, const float* __restrict__ W,
    float* __restrict__ out0, float* __restrict__ out1, int ld)
{
    __shared__ __align__(16) float sX[64][33];    // [m][k] scalar distinct reads
    __shared__ __align__(16) float sWT[32][68];   // [k][e] uniform float4 reads
    const int tid  = threadIdx.x;
    const int lane = tid & 31;
    const int warp = tid >> 5;
    if (blockIdx.x == 0 && tid < NE) g_cnt[tid] = 0;   // reset for top2

    const int part  = (NPARTS == 2) ? (blockIdx.x >> 7) : 0;
    const int bx    = (NPARTS == 2) ? (blockIdx.x & 127) : blockIdx.x;
    const int k_off = part * KLEN;
    float* outp     = part ? out1 : out0;

    const int m0 = bx * 64;
    const int eb = warp * 8;

    ull acc[2][4];
    #pragma unroll
    for (int i = 0; i < 2; i++)
        #pragma unroll
        for (int j = 0; j < 4; j++) acc[i][j] = 0ull;

    for (int kc = 0; kc < KLEN; kc += 32) {
        // stage X: 64x32 = 512 float4, 2 per thread
        #pragma unroll
        for (int rr = 0; rr < 2; rr++) {
            int f = tid + 256 * rr;
            int m = f >> 3, kl = (f & 7) * 4;
            float4 v = __ldg((const float4*)&X[(size_t)(m0 + m) * ld + k_off + kc + kl]);
            sX[m][kl]     = v.x;
            sX[m][kl + 1] = v.y;
            sX[m][kl + 2] = v.z;
            sX[m][kl + 3] = v.w;
        }
        // stage W transposed: 64x32 = 512 float4, 2 per thread
        #pragma unroll
        for (int rr = 0; rr < 2; rr++) {
            int f = tid + 256 * rr;
            int e = f >> 3, kl = (f & 7) * 4;
            float4 v = __ldg((const float4*)&W[(size_t)e * ld + k_off + kc + kl]);
            sWT[kl][e]     = v.x;
            sWT[kl + 1][e] = v.y;
            sWT[kl + 2][e] = v.z;
            sWT[kl + 3][e] = v.w;
        }
        __syncthreads();
        #pragma unroll
        for (int k = 0; k < 32; k++) {
            float x0 = sX[lane][k];
            float x1 = sX[lane + 32][k];
            ull xx0 = pack2(x0, x0);
            ull xx1 = pack2(x1, x1);
            ulonglong2 wa = *(const ulonglong2*)&sWT[k][eb];
            ulonglong2 wb = *(const ulonglong2*)&sWT[k][eb + 4];
            acc[0][0] = ffma2(xx0, wa.x, acc[0][0]);
            acc[0][1] = ffma2(xx0, wa.y, acc[0][1]);
            acc[0][2] = ffma2(xx0, wb.x, acc[0][2]);
            acc[0][3] = ffma2(xx0, wb.y, acc[0][3]);
            acc[1][0] = ffma2(xx1, wa.x, acc[1][0]);
            acc[1][1] = ffma2(xx1, wa.y, acc[1][1]);
            acc[1][2] = ffma2(xx1, wb.x, acc[1][2]);
            acc[1][3] = ffma2(xx1, wb.y, acc[1][3]);
        }
        __syncthreads();
    }
    #pragma unroll
    for (int mm = 0; mm < 2; mm++) {
        float2 u0 = unpack2(acc[mm][0]);
        float2 u1 = unpack2(acc[mm][1]);
        float2 u2 = unpack2(acc[mm][2]);
        float2 u3 = unpack2(acc[mm][3]);
        float* lg = &outp[(size_t)(m0 + lane + 32 * mm) * NE + eb];
        *(float4*)lg       = make_float4(u0.x, u0.y, u1.x, u1.y);
        *(float4*)(lg + 4) = make_float4(u2.x, u2.y, u3.x, u3.y);
    }
}

// ---------------------------------------------------------------------------
// Top-2 + softmax + per-expert list build.  One warp per token.
// lg2 != null: logits = lg + lg2 (deterministic K-split sum).
// ---------------------------------------------------------------------------
__global__ __launch_bounds__(256) void top2_kernel(
    const float* __restrict__ lg1, const float* __restrict__ lg2)
{
    const int t    = blockIdx.x * 8 + (threadIdx.x >> 5);
    const int lane = threadIdx.x & 31;
    float v0 = lg1[(size_t)t * NE + lane];
    float v1 = lg1[(size_t)t * NE + lane + 32];
    if (lg2) {
        v0 += lg2[(size_t)t * NE + lane];
        v1 += lg2[(size_t)t * NE + lane + 32];
    }

    float m1; int i1;
    if (v0 >= v1) { m1 = v0; i1 = lane; } else { m1 = v1; i1 = lane + 32; }
    #pragma unroll
    for (int off = 16; off > 0; off >>= 1) {
        float om = __shfl_xor_sync(0xffffffffu, m1, off);
        int   oi = __shfl_xor_sync(0xffffffffu, i1, off);
        if (om > m1 || (om == m1 && oi < i1)) { m1 = om; i1 = oi; }
    }
    float c0 = (lane == i1)      ? -INFINITY : v0;
    float c1 = (lane + 32 == i1) ? -INFINITY : v1;
    float m2; int i2;
    if (c0 >= c1) { m2 = c0; i2 = lane; } else { m2 = c1; i2 = lane + 32; }
    #pragma unroll
    for (int off = 16; off > 0; off >>= 1) {
        float om = __shfl_xor_sync(0xffffffffu, m2, off);
        int   oi = __shfl_xor_sync(0xffffffffu, i2, off);
        if (om > m2 || (om == m2 && oi < i2)) { m2 = om; i2 = oi; }
    }
    if (lane == 0) {
        float p1 = 1.f / (1.f + expf(m2 - m1));
        g_prob[2 * t]     = p1;
        g_prob[2 * t + 1] = 1.f - p1;
        int pos = atomicAdd(&g_cnt[i1], 1);
        g_list[i1 * NPAIR + pos] = 2 * t;
        pos = atomicAdd(&g_cnt[i2], 1);
        g_list[i2 * NPAIR + pos] = 2 * t + 1;
    }
}

// ---------------------------------------------------------------------------
// Chunk map
// ---------------------------------------------------------------------------
__global__ void prefix_kernel()
{
    __shared__ int s_c[NE];
    __shared__ int s_off[NE];
    const int e = threadIdx.x;     // 64 threads
    int c = (g_cnt[e] + TPB - 1) / TPB;
    s_c[e] = c;
    __syncthreads();
    if (e == 0) {
        int s = 0;
        for (int i = 0; i < NE; i++) { s_off[i] = s; s += s_c[i]; }
        g_nchunks = s;
    }
    __syncthreads();
    int o = s_off[e];
    for (int i = 0; i < c; i++)
        g_chunk[o + i] = make_int2(e, i * TPB);
}

// ---------------------------------------------------------------------------
// Up bilinear: 2 pairs/iter, FFMA2 inner loops.
// T(64x32) = A(64x32) X(32x32);  Y(64x64) = T B^T
// ---------------------------------------------------------------------------
__global__ __launch_bounds__(256) void bilinear_up(
    const float* __restrict__ x, const float* __restrict__ A, const float* __restrict__ B)
{
    const int b = blockIdx.x;
    if (b >= g_nchunks) return;
    const int2 ch   = g_chunk[b];
    const int e     = ch.x;
    const int start = ch.y;
    const int cnt   = g_cnt[e];
    const int tid   = threadIdx.x;
    const int lane  = tid & 31;
    const int warp  = tid >> 5;

    __shared__ __align__(16) float sAT[32][65];      // [i][o]
    __shared__ __align__(16) float sBT[32][65];      // [j][p]
    __shared__ __align__(16) float sX[2][32][32];    // [i][j]
    __shared__ __align__(16) float sTT[2][32][64];   // [j][o]

    {   // stage A [64][32] -> sAT[i][o], B -> sBT[j][p]
        const float4* a4 = (const float4*)(A + (size_t)e * 2048);
        const float4* b4 = (const float4*)(B + (size_t)e * 2048);
        #pragma unroll
        for (int rr = 0; rr < 2; rr++) {
            int f   = tid + 256 * rr;
            int row = f >> 3;            // o or p
            int col = (f & 7) * 4;       // i or j
            float4 av = __ldg(&a4[f]);
            sAT[col][row] = av.x; sAT[col+1][row] = av.y;
            sAT[col+2][row] = av.z; sAT[col+3][row] = av.w;
            float4 bv = __ldg(&b4[f]);
            sBT[col][row] = bv.x; sBT[col+1][row] = bv.y;
            sBT[col+2][row] = bv.z; sBT[col+3][row] = bv.w;
        }
    }

    const int jb = warp * 4;   // T phase: 4 j's
    const int ob = warp * 8;   // Y phase: 8 o's
    const int xi = tid >> 3;
    const int xj = (tid & 7) * 4;

    __syncthreads();

    for (int u = 0; u < TPB; u += 2) {
        int pi0 = start + u;
        if (pi0 >= cnt) break;                 // block-uniform
        int  pair0  = g_list[e * NPAIR + pi0];
        bool valid1 = (pi0 + 1 < cnt);
        int  pair1  = valid1 ? g_list[e * NPAIR + pi0 + 1] : pair0;
        int  t0 = pair0 >> 1, t1 = pair1 >> 1;

        float4 xv0 = __ldg((const float4*)&x[(size_t)t0 * 1024 + tid * 4]);
        float4 xv1 = __ldg((const float4*)&x[(size_t)t1 * 1024 + tid * 4]);
        *(float4*)&sX[0][xi][xj] = xv0;
        *(float4*)&sX[1][xi][xj] = xv1;
        __syncthreads();

        // ---- T phase: 8 FFMA2 + 2 scalar LDS + 2 LDS.128 per i ----
        {
            ull tacc[2][2][2];   // [pair][o-half][j-pair]
            #pragma unroll
            for (int p = 0; p < 2; p++)
                #pragma unroll
                for (int s = 0; s < 2; s++)
                    #pragma unroll
                    for (int q = 0; q < 2; q++) tacc[p][s][q] = 0ull;
            #pragma unroll
            for (int i = 0; i < 32; i++) {
                float a0 = sAT[i][lane];
                float a1 = sAT[i][lane + 32];
                ull aa0 = pack2(a0, a0);
                ull aa1 = pack2(a1, a1);
                ulonglong2 x0 = *(const ulonglong2*)&sX[0][i][jb];
                ulonglong2 x1 = *(const ulonglong2*)&sX[1][i][jb];
                tacc[0][0][0] = ffma2(aa0, x0.x, tacc[0][0][0]);
                tacc[0][0][1] = ffma2(aa0, x0.y, tacc[0][0][1]);
                tacc[0][1][0] = ffma2(aa1, x0.x, tacc[0][1][0]);
                tacc[0][1][1] = ffma2(aa1, x0.y, tacc[0][1][1]);
                tacc[1][0][0] = ffma2(aa0, x1.x, tacc[1][0][0]);
                tacc[1][0][1] = ffma2(aa0, x1.y, tacc[1][0][1]);
                tacc[1][1][0] = ffma2(aa1, x1.x, tacc[1][1][0]);
                tacc[1][1][1] = ffma2(aa1, x1.y, tacc[1][1][1]);
            }
            #pragma unroll
            for (int p = 0; p < 2; p++)
                #pragma unroll
                for (int s = 0; s < 2; s++) {
                    int col = lane + 32 * s;
                    float2 lo = unpack2(tacc[p][s][0]);
                    float2 hi = unpack2(tacc[p][s][1]);
                    sTT[p][jb + 0][col] = lo.x;
                    sTT[p][jb + 1][col] = lo.y;
                    sTT[p][jb + 2][col] = hi.x;
                    sTT[p][jb + 3][col] = hi.y;
                }
        }
        __syncthreads();

        // ---- Y phase: 16 FFMA2 + 2 scalar LDS + 4 LDS.128 per j ----
        {
            ull y[2][2][4];     // [pair][p-half][o-pair]
            #pragma unroll
            for (int p = 0; p < 2; p++)
                #pragma unroll
                for (int s = 0; s < 2; s++)
                    #pragma unroll
                    for (int q = 0; q < 4; q++) y[p][s][q] = 0ull;
            #pragma unroll
            for (int j = 0; j < 32; j++) {
                float b0 = sBT[j][lane];
                float b1 = sBT[j][lane + 32];
                ull bb0 = pack2(b0, b0);
                ull bb1 = pack2(b1, b1);
                ulonglong2 ta0 = *(const ulonglong2*)&sTT[0][j][ob];
                ulonglong2 tb0 = *(const ulonglong2*)&sTT[0][j][ob + 4];
                ulonglong2 ta1 = *(const ulonglong2*)&sTT[1][j][ob];
                ulonglong2 tb1 = *(const ulonglong2*)&sTT[1][j][ob + 4];
                y[0][0][0] = ffma2(ta0.x, bb0, y[0][0][0]);
                y[0][0][1] = ffma2(ta0.y, bb0, y[0][0][1]);
                y[0][0][2] = ffma2(tb0.x, bb0, y[0][0][2]);
                y[0][0][3] = ffma2(tb0.y, bb0, y[0][0][3]);
                y[0][1][0] = ffma2(ta0.x, bb1, y[0][1][0]);
                y[0][1][1] = ffma2(ta0.y, bb1, y[0][1][1]);
                y[0][1][2] = ffma2(tb0.x, bb1, y[0][1][2]);
                y[0][1][3] = ffma2(tb0.y, bb1, y[0][1][3]);
                y[1][0][0] = ffma2(ta1.x, bb0, y[1][0][0]);
                y[1][0][1] = ffma2(ta1.y, bb0, y[1][0][1]);
                y[1][0][2] = ffma2(tb1.x, bb0, y[1][0][2]);
                y[1][0][3] = ffma2(tb1.y, bb0, y[1][0][3]);
                y[1][1][0] = ffma2(ta1.x, bb1, y[1][1][0]);
                y[1][1][1] = ffma2(ta1.y, bb1, y[1][1][1]);
                y[1][1][2] = ffma2(tb1.x, bb1, y[1][1][2]);
                y[1][1][3] = ffma2(tb1.y, bb1, y[1][1][3]);
            }
            // packed over o: y[p][s][q] = (o=ob+2q, o=ob+2q+1) at column lane+32s
            float* y0 = &g_yup[(size_t)pair0 * 4096];
            #pragma unroll
            for (int s = 0; s < 2; s++)
                #pragma unroll
                for (int q = 0; q < 4; q++) {
                    float2 v = unpack2(y[0][s][q]);
                    y0[(ob + 2 * q)     * 64 + lane + 32 * s] = v.x;
                    y0[(ob + 2 * q + 1) * 64 + lane + 32 * s] = v.y;
                }
            if (valid1) {
                float* y1 = &g_yup[(size_t)pair1 * 4096];
                #pragma unroll
                for (int s = 0; s < 2; s++)
                    #pragma unroll
                    for (int q = 0; q < 4; q++) {
                        float2 v = unpack2(y[1][s][q]);
                        y1[(ob + 2 * q)     * 64 + lane + 32 * s] = v.x;
                        y1[(ob + 2 * q + 1) * 64 + lane + 32 * s] = v.y;
                    }
            }
        }
        __syncthreads();
    }
}

// ---------------------------------------------------------------------------
// Down bilinear: 2 pairs/iter, FFMA2 inner loops.
// T(32x64) = A(32x64) H(64x64);  Y(32x32) = T B^T
// ---------------------------------------------------------------------------
__global__ __launch_bounds__(256) void bilinear_down(
    const float* __restrict__ A, const float* __restrict__ B)
{
    const int b = blockIdx.x;
    if (b >= g_nchunks) return;
    const int2 ch   = g_chunk[b];
    const int e     = ch.x;
    const int start = ch.y;
    const int cnt   = g_cnt[e];
    const int tid   = threadIdx.x;
    const int lane  = tid & 31;
    const int warp  = tid >> 5;

    __shared__ __align__(16) float sAT[64][33];      // [i][o<32]
    __shared__ __align__(16) float sBT[64][33];      // [j][p<32]
    __shared__ __align__(16) float sH[2][64][64];    // [i][j]
    __shared__ __align__(16) float sTT[2][64][32];   // [j][o]

    {   // stage A [32][64] -> sAT[i][o], B -> sBT[j][p]
        const float4* a4 = (const float4*)(A + (size_t)e * 2048);
        const float4* b4 = (const float4*)(B + (size_t)e * 2048);
        #pragma unroll
        for (int rr = 0; rr < 2; rr++) {
            int f   = tid + 256 * rr;
            int row = f >> 4;            // o or p  (<32)
            int col = (f & 15) * 4;      // i or j
            float4 av = __ldg(&a4[f]);
            sAT[col][row] = av.x; sAT[col+1][row] = av.y;
            sAT[col+2][row] = av.z; sAT[col+3][row] = av.w;
            float4 bv = __ldg(&b4[f]);
            sBT[col][row] = bv.x; sBT[col+1][row] = bv.y;
            sBT[col+2][row] = bv.z; sBT[col+3][row] = bv.w;
        }
    }

    const int jb = warp * 8;   // T phase: 8 j's
    const int ob = warp * 4;   // Y phase: 4 o's

    __syncthreads();

    for (int u = 0; u < TPB; u += 2) {
        int pi0 = start + u;
        if (pi0 >= cnt) break;
        int  pair0  = g_list[e * NPAIR + pi0];
        bool valid1 = (pi0 + 1 < cnt);
        int  pair1  = valid1 ? g_list[e * NPAIR + pi0 + 1] : pair0;
        int  t0 = pair0 >> 1, t1 = pair1 >> 1;

        {
            const float4* h0 = (const float4*)&g_h[(size_t)t0 * 4096];
            const float4* h1 = (const float4*)&g_h[(size_t)t1 * 4096];
            #pragma unroll
            for (int rr = 0; rr < 4; rr++) {
                int f = tid + 256 * rr;
                *(float4*)&sH[0][f >> 4][(f & 15) * 4] = __ldg(&h0[f]);
                *(float4*)&sH[1][f >> 4][(f & 15) * 4] = __ldg(&h1[f]);
            }
        }
        __syncthreads();

        // ---- T phase: 8 FFMA2 + 1 scalar LDS + 4 LDS.128 per i ----
        {
            ull tacc[2][4];    // [pair][j-pair]  (8 j's)
            #pragma unroll
            for (int p = 0; p < 2; p++)
                #pragma unroll
                for (int q = 0; q < 4; q++) tacc[p][q] = 0ull;
            #pragma unroll
            for (int i = 0; i < 64; i++) {
                float a = sAT[i][lane];
                ull aa = pack2(a, a);
                ulonglong2 h0a = *(const ulonglong2*)&sH[0][i][jb];
                ulonglong2 h0b = *(const ulonglong2*)&sH[0][i][jb + 4];
                ulonglong2 h1a = *(const ulonglong2*)&sH[1][i][jb];
                ulonglong2 h1b = *(const ulonglong2*)&sH[1][i][jb + 4];
                tacc[0][0] = ffma2(aa, h0a.x, tacc[0][0]);
                tacc[0][1] = ffma2(aa, h0a.y, tacc[0][1]);
                tacc[0][2] = ffma2(aa, h0b.x, tacc[0][2]);
                tacc[0][3] = ffma2(aa, h0b.y, tacc[0][3]);
                tacc[1][0] = ffma2(aa, h1a.x, tacc[1][0]);
                tacc[1][1] = ffma2(aa, h1a.y, tacc[1][1]);
                tacc[1][2] = ffma2(aa, h1b.x, tacc[1][2]);
                tacc[1][3] = ffma2(aa, h1b.y, tacc[1][3]);
            }
            #pragma unroll
            for (int p = 0; p < 2; p++)
                #pragma unroll
                for (int q = 0; q < 4; q++) {
                    float2 v = unpack2(tacc[p][q]);
                    sTT[p][jb + 2 * q][lane]     = v.x;
                    sTT[p][jb + 2 * q + 1][lane] = v.y;
                }
        }
        __syncthreads();

        // ---- Y phase: 4 FFMA2 + 1 scalar LDS + 2 LDS.128 per j ----
        {
            ull y[2][2];       // [pair][o-pair]  (4 o's)
            y[0][0] = y[0][1] = y[1][0] = y[1][1] = 0ull;
            #pragma unroll
            for (int j = 0; j < 64; j++) {
                float bv = sBT[j][lane];
                ull bb = pack2(bv, bv);
                ulonglong2 t0v = *(const ulonglong2*)&sTT[0][j][ob];
                ulonglong2 t1v = *(const ulonglong2*)&sTT[1][j][ob];
                y[0][0] = ffma2(t0v.x, bb, y[0][0]);
                y[0][1] = ffma2(t0v.y, bb, y[0][1]);
                y[1][0] = ffma2(t1v.x, bb, y[1][0]);
                y[1][1] = ffma2(t1v.y, bb, y[1][1]);
            }
            float* yo0 = &g_ydown[(size_t)pair0 * 1024];
            #pragma unroll
            for (int q = 0; q < 2; q++) {
                float2 v = unpack2(y[0][q]);
                yo0[(ob + 2 * q)     * 32 + lane] = v.x;
                yo0[(ob + 2 * q + 1) * 32 + lane] = v.y;
            }
            if (valid1) {
                float* yo1 = &g_ydown[(size_t)pair1 * 1024];
                #pragma unroll
                for (int q = 0; q < 2; q++) {
                    float2 v = unpack2(y[1][q]);
                    yo1[(ob + 2 * q)     * 32 + lane] = v.x;
                    yo1[(ob + 2 * q + 1) * 32 + lane] = v.y;
                }
            }
        }
        __syncthreads();
    }
}

// ---------------------------------------------------------------------------
// Combine kernels
// ---------------------------------------------------------------------------
__global__ __launch_bounds__(256) void combine_up(
    const float* __restrict__ scale, const float* __restrict__ bias)
{
    const int t   = blockIdx.x;
    const int tid = threadIdx.x;
    const float p0 = g_prob[2 * t], p1 = g_prob[2 * t + 1];
    const float s  = __ldg(scale);
    const float4* y0 = (const float4*)&g_yup[(size_t)(2 * t) * 4096];
    const float4* y1 = (const float4*)&g_yup[(size_t)(2 * t + 1) * 4096];
    const float4* b4 = (const float4*)bias;
    float4* h4 = (float4*)&g_h[(size_t)t * 4096];
    #pragma unroll
    for (int rr = 0; rr < 4; rr++) {
        int f = tid + 256 * rr;
        float4 a = __ldg(&y0[f]), c = __ldg(&y1[f]), bb = __ldg(&b4[f]);
        float4 v;
        v.x = gelu_erf(s * (p0 * a.x + p1 * c.x) + bb.x);
        v.y = gelu_erf(s * (p0 * a.y + p1 * c.y) + bb.y);
        v.z = gelu_erf(s * (p0 * a.z + p1 * c.z) + bb.z);
        v.w = gelu_erf(s * (p0 * a.w + p1 * c.w) + bb.w);
        h4[f] = v;
    }
}

__global__ __launch_bounds__(256) void combine_down(
    const float* __restrict__ scale, const float* __restrict__ bias,
    float* __restrict__ out)
{
    const int t   = blockIdx.x;
    const int tid = threadIdx.x;
    const float p0 = g_prob[2 * t], p1 = g_prob[2 * t + 1];
    const float s  = __ldg(scale);
    const float4* y0 = (const float4*)&g_ydown[(size_t)(2 * t) * 1024];
    const float4* y1 = (const float4*)&g_ydown[(size_t)(2 * t + 1) * 1024];
    const float4* b4 = (const float4*)bias;
    float4 a = __ldg(&y0[tid]), c = __ldg(&y1[tid]), bb = __ldg(&b4[tid]);
    float4 v;
    v.x = s * (p0 * a.x + p1 * c.x) + bb.x;
    v.y = s * (p0 * a.y + p1 * c.y) + bb.y;
    v.z = s * (p0 * a.z + p1 * c.z) + bb.z;
    v.w = s * (p0 * a.w + p1 * c.w) + bb.w;
    ((float4*)&out[(size_t)t * 1024])[tid] = v;
}

// ---------------------------------------------------------------------------
extern "C" void kernel_launch(void* const* d_in, const int* in_sizes, int n_in,
                              void* d_out, int out_size)
{
    const float* x          = (const float*)d_in[0];
    const float* W_up       = (const float*)d_in[1];
    const float* A_up       = (const float*)d_in[2];
    const float* B_up       = (const float*)d_in[3];
    const float* scale_up   = (const float*)d_in[4];
    const float* bias_up    = (const float*)d_in[5];
    const float* W_down     = (const float*)d_in[6];
    const float* A_down     = (const float*)d_in[7];
    const float* B_down     = (const float*)d_in[8];
    const float* scale_down = (const float*)d_in[9];
    const float* bias_down  = (const float*)d_in[10];
    float*       out        = (float*)d_out;

    const int n_tok = in_sizes[0] / 1024;     // 8192

    float *h_ptr = nullptr, *lg1 = nullptr, *lg2 = nullptr;
    cudaGetSymbolAddress((void**)&h_ptr, g_h);
    cudaGetSymbolAddress((void**)&lg1, g_logits);
    cudaGetSymbolAddress((void**)&lg2, g_logits2);

    // ---- up ----
    router_gemm<1024, 1><<<n_tok / 64, 256>>>(x, W_up, lg1, nullptr, 1024);
    top2_kernel<<<n_tok / 8, 256>>>(lg1, nullptr);
    prefix_kernel<<<1, 64>>>();
    bilinear_up<<<MAXCHUNK, 256>>>(x, A_up, B_up);
    combine_up<<<n_tok, 256>>>(scale_up, bias_up);

    // ---- down (K split in 2 within one 256-block launch) ----
    router_gemm<2048, 2><<<2 * (n_tok / 64), 256>>>(h_ptr, W_down, lg1, lg2, 4096);
    top2_kernel<<<n_tok / 8, 256>>>(lg1, lg2);
    prefix_kernel<<<1, 64>>>();
    bilinear_down<<<MAXCHUNK, 256>>>(A_down, B_down);
    combine_down<<<n_tok, 256>>>(scale_down, bias_down, out);
}

// round 6
// speedup vs baseline: 1.4697x; 1.4697x over previous
#include <cuda_runtime.h>
#include <math.h>

#define NTOK   8192
#define NPAIR  (NTOK * 2)
#define NE     64
#define TPB    16
#define MAXCHUNK (NPAIR / TPB + NE)   // 1088

// ---- scratch (device globals; no allocs allowed) ----
__device__ float g_h[(size_t)NTOK * 4096];        // 134 MB
__device__ float g_yup[(size_t)NPAIR * 4096];     // 268 MB
__device__ float g_ydown[(size_t)NPAIR * 1024];   // 67 MB
__device__ float g_logits[(size_t)NTOK * NE];     // 2 MB
__device__ float g_logits2[(size_t)NTOK * NE];    // 2 MB (K-split partial)
__device__ float g_prob[NPAIR];
__device__ int   g_cnt[NE];
__device__ int   g_list[NE * NPAIR];              // 4 MB
__device__ int2  g_chunk[MAXCHUNK];
__device__ int   g_nchunks;

__device__ __forceinline__ float gelu_erf(float v) { return v * normcdff(v); }

// ---------------------------------------------------------------------------
// Router GEMM: logits[M,64] = X[M,Ktot] * W[64,Ktot]^T, 64-token tiles.
// NPARTS=2: grid doubles; upper half computes k in [KLEN,2*KLEN) -> out1.
// Inner loop per k: 2 distinct scalar LDS + 2 uniform LDS.128 + 16 FFMA.
// ---------------------------------------------------------------------------
template<int KLEN, int NPARTS>
__global__ __launch_bounds__(256) void router_gemm(
    const float* __restrict__ X, const float* __restrict__ W,
    float* __restrict__ out0, float* __restrict__ out1, int ld)
{
    __shared__ __align__(16) float sX[64][33];    // [m][k] scalar distinct reads
    __shared__ __align__(16) float sWT[32][68];   // [k][e] uniform float4 reads
    const int tid  = threadIdx.x;
    const int lane = tid & 31;
    const int warp = tid >> 5;
    if (blockIdx.x == 0 && tid < NE) g_cnt[tid] = 0;   // reset for top2

    const int part  = (NPARTS == 2) ? (blockIdx.x >> 7) : 0;
    const int bx    = (NPARTS == 2) ? (blockIdx.x & 127) : blockIdx.x;
    const int k_off = part * KLEN;
    float* outp     = part ? out1 : out0;

    const int m0 = bx * 64;
    const int eb = warp * 8;

    float acc[2][8];
    #pragma unroll
    for (int i = 0; i < 2; i++)
        #pragma unroll
        for (int j = 0; j < 8; j++) acc[i][j] = 0.f;

    for (int kc = 0; kc < KLEN; kc += 32) {
        // stage X: 64x32 = 512 float4, 2 per thread
        #pragma unroll
        for (int rr = 0; rr < 2; rr++) {
            int f = tid + 256 * rr;
            int m = f >> 3, kl = (f & 7) * 4;
            float4 v = __ldg((const float4*)&X[(size_t)(m0 + m) * ld + k_off + kc + kl]);
            sX[m][kl]     = v.x;
            sX[m][kl + 1] = v.y;
            sX[m][kl + 2] = v.z;
            sX[m][kl + 3] = v.w;
        }
        // stage W transposed: 64x32 = 512 float4, 2 per thread
        #pragma unroll
        for (int rr = 0; rr < 2; rr++) {
            int f = tid + 256 * rr;
            int e = f >> 3, kl = (f & 7) * 4;
            float4 v = __ldg((const float4*)&W[(size_t)e * ld + k_off + kc + kl]);
            sWT[kl][e]     = v.x;
            sWT[kl + 1][e] = v.y;
            sWT[kl + 2][e] = v.z;
            sWT[kl + 3][e] = v.w;
        }
        __syncthreads();
        #pragma unroll
        for (int k = 0; k < 32; k++) {
            float x0 = sX[lane][k];
            float x1 = sX[lane + 32][k];
            float4 wa = *(const float4*)&sWT[k][eb];
            float4 wb = *(const float4*)&sWT[k][eb + 4];
            acc[0][0] += x0 * wa.x; acc[0][1] += x0 * wa.y;
            acc[0][2] += x0 * wa.z; acc[0][3] += x0 * wa.w;
            acc[0][4] += x0 * wb.x; acc[0][5] += x0 * wb.y;
            acc[0][6] += x0 * wb.z; acc[0][7] += x0 * wb.w;
            acc[1][0] += x1 * wa.x; acc[1][1] += x1 * wa.y;
            acc[1][2] += x1 * wa.z; acc[1][3] += x1 * wa.w;
            acc[1][4] += x1 * wb.x; acc[1][5] += x1 * wb.y;
            acc[1][6] += x1 * wb.z; acc[1][7] += x1 * wb.w;
        }
        __syncthreads();
    }
    #pragma unroll
    for (int mm = 0; mm < 2; mm++) {
        float* lg = &outp[(size_t)(m0 + lane + 32 * mm) * NE + eb];
        *(float4*)lg       = make_float4(acc[mm][0], acc[mm][1], acc[mm][2], acc[mm][3]);
        *(float4*)(lg + 4) = make_float4(acc[mm][4], acc[mm][5], acc[mm][6], acc[mm][7]);
    }
}

// ---------------------------------------------------------------------------
// Top-2 + softmax + per-expert list build.  One warp per token.
// lg2 != null: logits = lg1 + lg2 (deterministic K-split sum).
// ---------------------------------------------------------------------------
__global__ __launch_bounds__(256) void top2_kernel(
    const float* __restrict__ lg1, const float* __restrict__ lg2)
{
    const int t    = blockIdx.x * 8 + (threadIdx.x >> 5);
    const int lane = threadIdx.x & 31;
    float v0 = lg1[(size_t)t * NE + lane];
    float v1 = lg1[(size_t)t * NE + lane + 32];
    if (lg2) {
        v0 += lg2[(size_t)t * NE + lane];
        v1 += lg2[(size_t)t * NE + lane + 32];
    }

    float m1; int i1;
    if (v0 >= v1) { m1 = v0; i1 = lane; } else { m1 = v1; i1 = lane + 32; }
    #pragma unroll
    for (int off = 16; off > 0; off >>= 1) {
        float om = __shfl_xor_sync(0xffffffffu, m1, off);
        int   oi = __shfl_xor_sync(0xffffffffu, i1, off);
        if (om > m1 || (om == m1 && oi < i1)) { m1 = om; i1 = oi; }
    }
    float c0 = (lane == i1)      ? -INFINITY : v0;
    float c1 = (lane + 32 == i1) ? -INFINITY : v1;
    float m2; int i2;
    if (c0 >= c1) { m2 = c0; i2 = lane; } else { m2 = c1; i2 = lane + 32; }
    #pragma unroll
    for (int off = 16; off > 0; off >>= 1) {
        float om = __shfl_xor_sync(0xffffffffu, m2, off);
        int   oi = __shfl_xor_sync(0xffffffffu, i2, off);
        if (om > m2 || (om == m2 && oi < i2)) { m2 = om; i2 = oi; }
    }
    if (lane == 0) {
        float p1 = 1.f / (1.f + expf(m2 - m1));
        g_prob[2 * t]     = p1;
        g_prob[2 * t + 1] = 1.f - p1;
        int pos = atomicAdd(&g_cnt[i1], 1);
        g_list[i1 * NPAIR + pos] = 2 * t;
        pos = atomicAdd(&g_cnt[i2], 1);
        g_list[i2 * NPAIR + pos] = 2 * t + 1;
    }
}

// ---------------------------------------------------------------------------
// Chunk map
// ---------------------------------------------------------------------------
__global__ void prefix_kernel()
{
    __shared__ int s_c[NE];
    __shared__ int s_off[NE];
    const int e = threadIdx.x;     // 64 threads
    int c = (g_cnt[e] + TPB - 1) / TPB;
    s_c[e] = c;
    __syncthreads();
    if (e == 0) {
        int s = 0;
        for (int i = 0; i < NE; i++) { s_off[i] = s; s += s_c[i]; }
        g_nchunks = s;
    }
    __syncthreads();
    int o = s_off[e];
    for (int i = 0; i < c; i++)
        g_chunk[o + i] = make_int2(e, i * TPB);
}

// ---------------------------------------------------------------------------
// Up bilinear (R3 version, plain FFMA): 2 pairs per iteration.
// T(64x32) = A(64x32) X(32x32);  Y(64x64) = T B^T
// T phase: o = {lane,lane+32} distinct scalar; j uniform float4. 4wf/16 FFMA.
// Y phase: p = {lane,lane+32} distinct scalar; o uniform float4. 6wf/32 FFMA.
// ---------------------------------------------------------------------------
__global__ __launch_bounds__(256) void bilinear_up(
    const float* __restrict__ x, const float* __restrict__ A, const float* __restrict__ B)
{
    const int b = blockIdx.x;
    if (b >= g_nchunks) return;
    const int2 ch   = g_chunk[b];
    const int e     = ch.x;
    const int start = ch.y;
    const int cnt   = g_cnt[e];
    const int tid   = threadIdx.x;
    const int lane  = tid & 31;
    const int warp  = tid >> 5;

    __shared__ __align__(16) float sAT[32][65];      // [i][o]
    __shared__ __align__(16) float sBT[32][65];      // [j][p]
    __shared__ __align__(16) float sX[2][32][32];    // [i][j]
    __shared__ __align__(16) float sTT[2][32][64];   // [j][o]

    {   // stage A [64][32] -> sAT[i][o], B -> sBT[j][p]
        const float4* a4 = (const float4*)(A + (size_t)e * 2048);
        const float4* b4 = (const float4*)(B + (size_t)e * 2048);
        #pragma unroll
        for (int rr = 0; rr < 2; rr++) {
            int f   = tid + 256 * rr;
            int row = f >> 3;            // o or p
            int col = (f & 7) * 4;       // i or j
            float4 av = __ldg(&a4[f]);
            sAT[col][row] = av.x; sAT[col+1][row] = av.y;
            sAT[col+2][row] = av.z; sAT[col+3][row] = av.w;
            float4 bv = __ldg(&b4[f]);
            sBT[col][row] = bv.x; sBT[col+1][row] = bv.y;
            sBT[col+2][row] = bv.z; sBT[col+3][row] = bv.w;
        }
    }

    const int jb = warp * 4;   // T phase: 4 j's
    const int ob = warp * 8;   // Y phase: 8 o's
    const int xi = tid >> 3;
    const int xj = (tid & 7) * 4;

    __syncthreads();

    for (int u = 0; u < TPB; u += 2) {
        int pi0 = start + u;
        if (pi0 >= cnt) break;                 // block-uniform
        int  pair0  = g_list[e * NPAIR + pi0];
        bool valid1 = (pi0 + 1 < cnt);
        int  pair1  = valid1 ? g_list[e * NPAIR + pi0 + 1] : pair0;
        int  t0 = pair0 >> 1, t1 = pair1 >> 1;

        float4 xv0 = __ldg((const float4*)&x[(size_t)t0 * 1024 + tid * 4]);
        float4 xv1 = __ldg((const float4*)&x[(size_t)t1 * 1024 + tid * 4]);
        *(float4*)&sX[0][xi][xj] = xv0;
        *(float4*)&sX[1][xi][xj] = xv1;
        __syncthreads();

        // ---- T phase ----
        {
            float tacc[2][2][4];
            #pragma unroll
            for (int p = 0; p < 2; p++)
                #pragma unroll
                for (int s = 0; s < 2; s++)
                    #pragma unroll
                    for (int j = 0; j < 4; j++) tacc[p][s][j] = 0.f;
            #pragma unroll
            for (int i = 0; i < 32; i++) {
                float a0 = sAT[i][lane];
                float a1 = sAT[i][lane + 32];
                float4 x0 = *(const float4*)&sX[0][i][jb];
                float4 x1 = *(const float4*)&sX[1][i][jb];
                tacc[0][0][0] += a0*x0.x; tacc[0][0][1] += a0*x0.y; tacc[0][0][2] += a0*x0.z; tacc[0][0][3] += a0*x0.w;
                tacc[0][1][0] += a1*x0.x; tacc[0][1][1] += a1*x0.y; tacc[0][1][2] += a1*x0.z; tacc[0][1][3] += a1*x0.w;
                tacc[1][0][0] += a0*x1.x; tacc[1][0][1] += a0*x1.y; tacc[1][0][2] += a0*x1.z; tacc[1][0][3] += a0*x1.w;
                tacc[1][1][0] += a1*x1.x; tacc[1][1][1] += a1*x1.y; tacc[1][1][2] += a1*x1.z; tacc[1][1][3] += a1*x1.w;
            }
            #pragma unroll
            for (int p = 0; p < 2; p++)
                #pragma unroll
                for (int jj = 0; jj < 4; jj++) {
                    sTT[p][jb + jj][lane]      = tacc[p][0][jj];
                    sTT[p][jb + jj][lane + 32] = tacc[p][1][jj];
                }
        }
        __syncthreads();

        // ---- Y phase ----
        {
            float y[2][2][8];
            #pragma unroll
            for (int p = 0; p < 2; p++)
                #pragma unroll
                for (int s = 0; s < 2; s++)
                    #pragma unroll
                    for (int oo = 0; oo < 8; oo++) y[p][s][oo] = 0.f;
            #pragma unroll
            for (int j = 0; j < 32; j++) {
                float b0 = sBT[j][lane];
                float b1 = sBT[j][lane + 32];
                float4 ta0 = *(const float4*)&sTT[0][j][ob];
                float4 tb0 = *(const float4*)&sTT[0][j][ob + 4];
                float4 ta1 = *(const float4*)&sTT[1][j][ob];
                float4 tb1 = *(const float4*)&sTT[1][j][ob + 4];
                y[0][0][0] += ta0.x*b0; y[0][0][1] += ta0.y*b0; y[0][0][2] += ta0.z*b0; y[0][0][3] += ta0.w*b0;
                y[0][0][4] += tb0.x*b0; y[0][0][5] += tb0.y*b0; y[0][0][6] += tb0.z*b0; y[0][0][7] += tb0.w*b0;
                y[0][1][0] += ta0.x*b1; y[0][1][1] += ta0.y*b1; y[0][1][2] += ta0.z*b1; y[0][1][3] += ta0.w*b1;
                y[0][1][4] += tb0.x*b1; y[0][1][5] += tb0.y*b1; y[0][1][6] += tb0.z*b1; y[0][1][7] += tb0.w*b1;
                y[1][0][0] += ta1.x*b0; y[1][0][1] += ta1.y*b0; y[1][0][2] += ta1.z*b0; y[1][0][3] += ta1.w*b0;
                y[1][0][4] += tb1.x*b0; y[1][0][5] += tb1.y*b0; y[1][0][6] += tb1.z*b0; y[1][0][7] += tb1.w*b0;
                y[1][1][0] += ta1.x*b1; y[1][1][1] += ta1.y*b1; y[1][1][2] += ta1.z*b1; y[1][1][3] += ta1.w*b1;
                y[1][1][4] += tb1.x*b1; y[1][1][5] += tb1.y*b1; y[1][1][6] += tb1.z*b1; y[1][1][7] += tb1.w*b1;
            }
            // coalesced scalar stores: lanes contiguous in p
            float* y0 = &g_yup[(size_t)pair0 * 4096];
            #pragma unroll
            for (int oo = 0; oo < 8; oo++) {
                y0[(ob + oo) * 64 + lane]      = y[0][0][oo];
                y0[(ob + oo) * 64 + lane + 32] = y[0][1][oo];
            }
            if (valid1) {
                float* y1 = &g_yup[(size_t)pair1 * 4096];
                #pragma unroll
                for (int oo = 0; oo < 8; oo++) {
                    y1[(ob + oo) * 64 + lane]      = y[1][0][oo];
                    y1[(ob + oo) * 64 + lane + 32] = y[1][1][oo];
                }
            }
        }
        __syncthreads();
    }
}

// ---------------------------------------------------------------------------
// Down bilinear (R3 version, plain FFMA): 2 pairs per iteration.
// T(32x64) = A(32x64) H(64x64);  Y(32x32) = T B^T
// ---------------------------------------------------------------------------
__global__ __launch_bounds__(256) void bilinear_down(
    const float* __restrict__ A, const float* __restrict__ B)
{
    const int b = blockIdx.x;
    if (b >= g_nchunks) return;
    const int2 ch   = g_chunk[b];
    const int e     = ch.x;
    const int start = ch.y;
    const int cnt   = g_cnt[e];
    const int tid   = threadIdx.x;
    const int lane  = tid & 31;
    const int warp  = tid >> 5;

    __shared__ __align__(16) float sAT[64][33];      // [i][o<32]
    __shared__ __align__(16) float sBT[64][33];      // [j][p<32]
    __shared__ __align__(16) float sH[2][64][64];    // [i][j]
    __shared__ __align__(16) float sTT[2][64][32];   // [j][o]

    {   // stage A [32][64] -> sAT[i][o], B -> sBT[j][p]
        const float4* a4 = (const float4*)(A + (size_t)e * 2048);
        const float4* b4 = (const float4*)(B + (size_t)e * 2048);
        #pragma unroll
        for (int rr = 0; rr < 2; rr++) {
            int f   = tid + 256 * rr;
            int row = f >> 4;            // o or p  (<32)
            int col = (f & 15) * 4;      // i or j
            float4 av = __ldg(&a4[f]);
            sAT[col][row] = av.x; sAT[col+1][row] = av.y;
            sAT[col+2][row] = av.z; sAT[col+3][row] = av.w;
            float4 bv = __ldg(&b4[f]);
            sBT[col][row] = bv.x; sBT[col+1][row] = bv.y;
            sBT[col+2][row] = bv.z; sBT[col+3][row] = bv.w;
        }
    }

    const int jb = warp * 8;   // T phase: 8 j's
    const int ob = warp * 4;   // Y phase: 4 o's

    __syncthreads();

    for (int u = 0; u < TPB; u += 2) {
        int pi0 = start + u;
        if (pi0 >= cnt) break;
        int  pair0  = g_list[e * NPAIR + pi0];
        bool valid1 = (pi0 + 1 < cnt);
        int  pair1  = valid1 ? g_list[e * NPAIR + pi0 + 1] : pair0;
        int  t0 = pair0 >> 1, t1 = pair1 >> 1;

        {
            const float4* h0 = (const float4*)&g_h[(size_t)t0 * 4096];
            const float4* h1 = (const float4*)&g_h[(size_t)t1 * 4096];
            #pragma unroll
            for (int rr = 0; rr < 4; rr++) {
                int f = tid + 256 * rr;
                *(float4*)&sH[0][f >> 4][(f & 15) * 4] = __ldg(&h0[f]);
                *(float4*)&sH[1][f >> 4][(f & 15) * 4] = __ldg(&h1[f]);
            }
        }
        __syncthreads();

        // ---- T phase: o = lane (distinct), 8 j uniform ----
        {
            float tacc[2][8];
            #pragma unroll
            for (int p = 0; p < 2; p++)
                #pragma unroll
                for (int j = 0; j < 8; j++) tacc[p][j] = 0.f;
            #pragma unroll
            for (int i = 0; i < 64; i++) {
                float a = sAT[i][lane];
                float4 h0a = *(const float4*)&sH[0][i][jb];
                float4 h0b = *(const float4*)&sH[0][i][jb + 4];
                float4 h1a = *(const float4*)&sH[1][i][jb];
                float4 h1b = *(const float4*)&sH[1][i][jb + 4];
                tacc[0][0] += a*h0a.x; tacc[0][1] += a*h0a.y; tacc[0][2] += a*h0a.z; tacc[0][3] += a*h0a.w;
                tacc[0][4] += a*h0b.x; tacc[0][5] += a*h0b.y; tacc[0][6] += a*h0b.z; tacc[0][7] += a*h0b.w;
                tacc[1][0] += a*h1a.x; tacc[1][1] += a*h1a.y; tacc[1][2] += a*h1a.z; tacc[1][3] += a*h1a.w;
                tacc[1][4] += a*h1b.x; tacc[1][5] += a*h1b.y; tacc[1][6] += a*h1b.z; tacc[1][7] += a*h1b.w;
            }
            #pragma unroll
            for (int p = 0; p < 2; p++)
                #pragma unroll
                for (int jj = 0; jj < 8; jj++)
                    sTT[p][jb + jj][lane] = tacc[p][jj];
        }
        __syncthreads();

        // ---- Y phase: p = lane (distinct), 4 o uniform ----
        {
            float y[2][4];
            #pragma unroll
            for (int p = 0; p < 2; p++)
                #pragma unroll
                for (int oo = 0; oo < 4; oo++) y[p][oo] = 0.f;
            #pragma unroll
            for (int j = 0; j < 64; j++) {
                float bv = sBT[j][lane];
                float4 t0v = *(const float4*)&sTT[0][j][ob];
                float4 t1v = *(const float4*)&sTT[1][j][ob];
                y[0][0] += t0v.x*bv; y[0][1] += t0v.y*bv; y[0][2] += t0v.z*bv; y[0][3] += t0v.w*bv;
                y[1][0] += t1v.x*bv; y[1][1] += t1v.y*bv; y[1][2] += t1v.z*bv; y[1][3] += t1v.w*bv;
            }
            float* yo0 = &g_ydown[(size_t)pair0 * 1024];
            #pragma unroll
            for (int oo = 0; oo < 4; oo++)
                yo0[(ob + oo) * 32 + lane] = y[0][oo];
            if (valid1) {
                float* yo1 = &g_ydown[(size_t)pair1 * 1024];
                #pragma unroll
                for (int oo = 0; oo < 4; oo++)
                    yo1[(ob + oo) * 32 + lane] = y[1][oo];
            }
        }
        __syncthreads();
    }
}

// ---------------------------------------------------------------------------
// Combine kernels
// ---------------------------------------------------------------------------
__global__ __launch_bounds__(256) void combine_up(
    const float* __restrict__ scale, const float* __restrict__ bias)
{
    const int t   = blockIdx.x;
    const int tid = threadIdx.x;
    const float p0 = g_prob[2 * t], p1 = g_prob[2 * t + 1];
    const float s  = __ldg(scale);
    const float4* y0 = (const float4*)&g_yup[(size_t)(2 * t) * 4096];
    const float4* y1 = (const float4*)&g_yup[(size_t)(2 * t + 1) * 4096];
    const float4* b4 = (const float4*)bias;
    float4* h4 = (float4*)&g_h[(size_t)t * 4096];
    #pragma unroll
    for (int rr = 0; rr < 4; rr++) {
        int f = tid + 256 * rr;
        float4 a = __ldg(&y0[f]), c = __ldg(&y1[f]), bb = __ldg(&b4[f]);
        float4 v;
        v.x = gelu_erf(s * (p0 * a.x + p1 * c.x) + bb.x);
        v.y = gelu_erf(s * (p0 * a.y + p1 * c.y) + bb.y);
        v.z = gelu_erf(s * (p0 * a.z + p1 * c.z) + bb.z);
        v.w = gelu_erf(s * (p0 * a.w + p1 * c.w) + bb.w);
        h4[f] = v;
    }
}

__global__ __launch_bounds__(256) void combine_down(
    const float* __restrict__ scale, const float* __restrict__ bias,
    float* __restrict__ out)
{
    const int t   = blockIdx.x;
    const int tid = threadIdx.x;
    const float p0 = g_prob[2 * t], p1 = g_prob[2 * t + 1];
    const float s  = __ldg(scale);
    const float4* y0 = (const float4*)&g_ydown[(size_t)(2 * t) * 1024];
    const float4* y1 = (const float4*)&g_ydown[(size_t)(2 * t + 1) * 1024];
    const float4* b4 = (const float4*)bias;
    float4 a = __ldg(&y0[tid]), c = __ldg(&y1[tid]), bb = __ldg(&b4[tid]);
    float4 v;
    v.x = s * (p0 * a.x + p1 * c.x) + bb.x;
    v.y = s * (p0 * a.y + p1 * c.y) + bb.y;
    v.z = s * (p0 * a.z + p1 * c.z) + bb.z;
    v.w = s * (p0 * a.w + p1 * c.w) + bb.w;
    ((float4*)&out[(size_t)t * 1024])[tid] = v;
}

// ---------------------------------------------------------------------------
extern "C" void kernel_launch(void* const* d_in, const int* in_sizes, int n_in,
                              void* d_out, int out_size)
{
    const float* x          = (const float*)d_in[0];
    const float* W_up       = (const float*)d_in[1];
    const float* A_up       = (const float*)d_in[2];
    const float* B_up       = (const float*)d_in[3];
    const float* scale_up   = (const float*)d_in[4];
    const float* bias_up    = (const float*)d_in[5];
    const float* W_down     = (const float*)d_in[6];
    const float* A_down     = (const float*)d_in[7];
    const float* B_down     = (const float*)d_in[8];
    const float* scale_down = (const float*)d_in[9];
    const float* bias_down  = (const float*)d_in[10];
    float*       out        = (float*)d_out;

    const int n_tok = in_sizes[0] / 1024;     // 8192

    float *h_ptr = nullptr, *lg1 = nullptr, *lg2 = nullptr;
    cudaGetSymbolAddress((void**)&h_ptr, g_h);
    cudaGetSymbolAddress((void**)&lg1, g_logits);
    cudaGetSymbolAddress((void**)&lg2, g_logits2);

    // ---- up ----
    router_gemm<1024, 1><<<n_tok / 64, 256>>>(x, W_up, lg1, nullptr, 1024);
    top2_kernel<<<n_tok / 8, 256>>>(lg1, nullptr);
    prefix_kernel<<<1, 64>>>();
    bilinear_up<<<MAXCHUNK, 256>>>(x, A_up, B_up);
    combine_up<<<n_tok, 256>>>(scale_up, bias_up);

    // ---- down (K split in 2 within one 256-block launch) ----
    router_gemm<2048, 2><<<2 * (n_tok / 64), 256>>>(h_ptr, W_down, lg1, lg2, 4096);
    top2_kernel<<<n_tok / 8, 256>>>(lg1, lg2);
    prefix_kernel<<<1, 64>>>();
    bilinear_down<<<MAXCHUNK, 256>>>(A_down, B_down);
    combine_down<<<n_tok, 256>>>(scale_down, bias_down, out);
}

// round 7
// speedup vs baseline: 1.7046x; 1.1599x over previous
#include <cuda_runtime.h>
#include <cuda_bf16.h>
#include <math.h>

#define NTOK   8192
#define NPAIR  (NTOK * 2)
#define NE     64
#define TPB    16
#define MAXCHUNK (NPAIR / TPB + NE)   // 1088

// ---- scratch (device globals; no allocs allowed) ----
__device__ float g_h[(size_t)NTOK * 4096];        // 134 MB
__device__ float g_yup[(size_t)NPAIR * 4096];     // 268 MB
__device__ float g_ydown[(size_t)NPAIR * 1024];   // 67 MB
__device__ float g_logits[(size_t)NTOK * NE];     // 2 MB
__device__ float g_logits2[(size_t)NTOK * NE];    // 2 MB (K-split partial)
__device__ float g_prob[NPAIR];
__device__ int   g_cnt[NE];
__device__ int   g_list[NE * NPAIR];              // 4 MB
__device__ int2  g_chunk[MAXCHUNK];
__device__ int   g_nchunks;

__device__ __forceinline__ float gelu_erf(float v) { return v * normcdff(v); }

// split fp32 into bf16 hi + bf16 lo (v ~= hi + lo, |resid| <~ 2^-18 |v|)
__device__ __forceinline__ void split_bf16(float v, __nv_bfloat16& h, __nv_bfloat16& l) {
    h = __float2bfloat16_rn(v);
    l = __float2bfloat16_rn(v - __bfloat162float(h));
}

// one m16n8k16 bf16 mma, fp32 accumulate (in place)
__device__ __forceinline__ void mma_bf16(float* d, const unsigned* a, const unsigned* b) {
    asm volatile(
        "mma.sync.aligned.m16n8k16.row.col.f32.bf16.bf16.f32 "
        "{%0,%1,%2,%3}, {%4,%5,%6,%7}, {%8,%9}, {%0,%1,%2,%3};"
        : "+f"(d[0]), "+f"(d[1]), "+f"(d[2]), "+f"(d[3])
        : "r"(a[0]), "r"(a[1]), "r"(a[2]), "r"(a[3]), "r"(b[0]), "r"(b[1]));
}

// ---------------------------------------------------------------------------
// Router GEMM (unchanged fp32-exact): logits = X W^T, 64-token tiles.
// ---------------------------------------------------------------------------
template<int KLEN, int NPARTS>
__global__ __launch_bounds__(256) void router_gemm(
    const float* __restrict__ X, const float* __restrict__ W,
    float* __restrict__ out0, float* __restrict__ out1, int ld)
{
    __shared__ __align__(16) float sX[64][33];
    __shared__ __align__(16) float sWT[32][68];
    const int tid  = threadIdx.x;
    const int lane = tid & 31;
    const int warp = tid >> 5;
    if (blockIdx.x == 0 && tid < NE) g_cnt[tid] = 0;

    const int part  = (NPARTS == 2) ? (blockIdx.x >> 7) : 0;
    const int bx    = (NPARTS == 2) ? (blockIdx.x & 127) : blockIdx.x;
    const int k_off = part * KLEN;
    float* outp     = part ? out1 : out0;

    const int m0 = bx * 64;
    const int eb = warp * 8;

    float acc[2][8];
    #pragma unroll
    for (int i = 0; i < 2; i++)
        #pragma unroll
        for (int j = 0; j < 8; j++) acc[i][j] = 0.f;

    for (int kc = 0; kc < KLEN; kc += 32) {
        #pragma unroll
        for (int rr = 0; rr < 2; rr++) {
            int f = tid + 256 * rr;
            int m = f >> 3, kl = (f & 7) * 4;
            float4 v = __ldg((const float4*)&X[(size_t)(m0 + m) * ld + k_off + kc + kl]);
            sX[m][kl] = v.x; sX[m][kl+1] = v.y; sX[m][kl+2] = v.z; sX[m][kl+3] = v.w;
        }
        #pragma unroll
        for (int rr = 0; rr < 2; rr++) {
            int f = tid + 256 * rr;
            int e = f >> 3, kl = (f & 7) * 4;
            float4 v = __ldg((const float4*)&W[(size_t)e * ld + k_off + kc + kl]);
            sWT[kl][e] = v.x; sWT[kl+1][e] = v.y; sWT[kl+2][e] = v.z; sWT[kl+3][e] = v.w;
        }
        __syncthreads();
        #pragma unroll
        for (int k = 0; k < 32; k++) {
            float x0 = sX[lane][k];
            float x1 = sX[lane + 32][k];
            float4 wa = *(const float4*)&sWT[k][eb];
            float4 wb = *(const float4*)&sWT[k][eb + 4];
            acc[0][0] += x0*wa.x; acc[0][1] += x0*wa.y; acc[0][2] += x0*wa.z; acc[0][3] += x0*wa.w;
            acc[0][4] += x0*wb.x; acc[0][5] += x0*wb.y; acc[0][6] += x0*wb.z; acc[0][7] += x0*wb.w;
            acc[1][0] += x1*wa.x; acc[1][1] += x1*wa.y; acc[1][2] += x1*wa.z; acc[1][3] += x1*wa.w;
            acc[1][4] += x1*wb.x; acc[1][5] += x1*wb.y; acc[1][6] += x1*wb.z; acc[1][7] += x1*wb.w;
        }
        __syncthreads();
    }
    #pragma unroll
    for (int mm = 0; mm < 2; mm++) {
        float* lg = &outp[(size_t)(m0 + lane + 32 * mm) * NE + eb];
        *(float4*)lg       = make_float4(acc[mm][0], acc[mm][1], acc[mm][2], acc[mm][3]);
        *(float4*)(lg + 4) = make_float4(acc[mm][4], acc[mm][5], acc[mm][6], acc[mm][7]);
    }
}

// ---------------------------------------------------------------------------
// Top-2 + softmax + per-expert list build (unchanged).
// ---------------------------------------------------------------------------
__global__ __launch_bounds__(256) void top2_kernel(
    const float* __restrict__ lg1, const float* __restrict__ lg2)
{
    const int t    = blockIdx.x * 8 + (threadIdx.x >> 5);
    const int lane = threadIdx.x & 31;
    float v0 = lg1[(size_t)t * NE + lane];
    float v1 = lg1[(size_t)t * NE + lane + 32];
    if (lg2) {
        v0 += lg2[(size_t)t * NE + lane];
        v1 += lg2[(size_t)t * NE + lane + 32];
    }

    float m1; int i1;
    if (v0 >= v1) { m1 = v0; i1 = lane; } else { m1 = v1; i1 = lane + 32; }
    #pragma unroll
    for (int off = 16; off > 0; off >>= 1) {
        float om = __shfl_xor_sync(0xffffffffu, m1, off);
        int   oi = __shfl_xor_sync(0xffffffffu, i1, off);
        if (om > m1 || (om == m1 && oi < i1)) { m1 = om; i1 = oi; }
    }
    float c0 = (lane == i1)      ? -INFINITY : v0;
    float c1 = (lane + 32 == i1) ? -INFINITY : v1;
    float m2; int i2;
    if (c0 >= c1) { m2 = c0; i2 = lane; } else { m2 = c1; i2 = lane + 32; }
    #pragma unroll
    for (int off = 16; off > 0; off >>= 1) {
        float om = __shfl_xor_sync(0xffffffffu, m2, off);
        int   oi = __shfl_xor_sync(0xffffffffu, i2, off);
        if (om > m2 || (om == m2 && oi < i2)) { m2 = om; i2 = oi; }
    }
    if (lane == 0) {
        float p1 = 1.f / (1.f + expf(m2 - m1));
        g_prob[2 * t]     = p1;
        g_prob[2 * t + 1] = 1.f - p1;
        int pos = atomicAdd(&g_cnt[i1], 1);
        g_list[i1 * NPAIR + pos] = 2 * t;
        pos = atomicAdd(&g_cnt[i2], 1);
        g_list[i2 * NPAIR + pos] = 2 * t + 1;
    }
}

__global__ void prefix_kernel()
{
    __shared__ int s_c[NE];
    __shared__ int s_off[NE];
    const int e = threadIdx.x;
    int c = (g_cnt[e] + TPB - 1) / TPB;
    s_c[e] = c;
    __syncthreads();
    if (e == 0) {
        int s = 0;
        for (int i = 0; i < NE; i++) { s_off[i] = s; s += s_c[i]; }
        g_nchunks = s;
    }
    __syncthreads();
    int o = s_off[e];
    for (int i = 0; i < c; i++)
        g_chunk[o + i] = make_int2(e, i * TPB);
}

// ---------------------------------------------------------------------------
// Up bilinear, tensor-core version.
// Per pair: T(64x32) = A(64x32) X(32x32), Y(64x64) = T B^T, all via
// m16n8k16 bf16 mma with hi/lo 3-product K-concat.
// Operand smem layout: [row][hi cols | pad | lo cols], pitch 72 bf16
// (pitch = 36 words == 4 mod 32 -> fragment loads bank-conflict-free).
// 2 pairs per iteration: warps 0-3 pair0, warps 4-7 pair1.
// ---------------------------------------------------------------------------
__global__ __launch_bounds__(256) void bilinear_up(
    const float* __restrict__ x, const float* __restrict__ A, const float* __restrict__ B)
{
    const int b = blockIdx.x;
    if (b >= g_nchunks) return;
    const int2 ch   = g_chunk[b];
    const int e     = ch.x;
    const int start = ch.y;
    const int cnt   = g_cnt[e];
    const int tid   = threadIdx.x;
    const int lane  = tid & 31;
    const int warp  = tid >> 5;
    const int gid   = lane >> 2;    // 0..7
    const int tig   = lane & 3;     // 0..3

    __shared__ __align__(16) __nv_bfloat16 sA[64][72];     // A-op: [o][ihi 0-31 | ilo 36-67]
    __shared__ __align__(16) __nv_bfloat16 sB[64][72];     // B-op: [p][jhi | jlo]
    __shared__ __align__(16) __nv_bfloat16 sXT[2][32][72]; // B-op: [j][ihi | ilo]  (X^T)
    __shared__ __align__(16) __nv_bfloat16 sT[2][64][72];  // A-op: [o][jhi | jlo]

    // stage A_up[e] (64x32) and B_up[e] (64x32) hi/lo
    {
        const float4* a4 = (const float4*)(A + (size_t)e * 2048);
        const float4* b4 = (const float4*)(B + (size_t)e * 2048);
        #pragma unroll
        for (int rr = 0; rr < 2; rr++) {
            int f = tid + 256 * rr;
            int row = f >> 3, c0 = (f & 7) * 4;
            float4 av = __ldg(&a4[f]);
            float4 bv = __ldg(&b4[f]);
            float aa[4] = {av.x, av.y, av.z, av.w};
            float bb[4] = {bv.x, bv.y, bv.z, bv.w};
            #pragma unroll
            for (int q = 0; q < 4; q++) {
                __nv_bfloat16 h, l;
                split_bf16(aa[q], h, l);
                sA[row][c0 + q] = h; sA[row][36 + c0 + q] = l;
                split_bf16(bb[q], h, l);
                sB[row][c0 + q] = h; sB[row][36 + c0 + q] = l;
            }
        }
    }

    // k-step offset tables (element offsets): (AhXh)(AlXh)(AhXl)
    const int AOFF[6] = {0, 16, 36, 52, 0, 16};
    const int BOFF[6] = {0, 16, 0, 16, 36, 52};

    const int pl = warp >> 2;      // local pair 0/1
    const int mt = warp & 3;       // m-tile
    const int R  = mt * 16;

    for (int u = 0; u < TPB; u += 2) {
        int pi0 = start + u;
        if (pi0 >= cnt) break;                 // block-uniform
        int  pair0  = g_list[e * NPAIR + pi0];
        bool valid1 = (pi0 + 1 < cnt);
        int  pair1  = valid1 ? g_list[e * NPAIR + pi0 + 1] : pair0;
        const int myPair = pl ? pair1 : pair0;
        const bool myValid = (pl == 0) || valid1;

        // ---- stage X^T hi/lo for both pairs ----
        {
            int ts[2] = {pair0 >> 1, pair1 >> 1};
            int i = tid >> 3, j0 = (tid & 7) * 4;
            #pragma unroll
            for (int pp = 0; pp < 2; pp++) {
                float4 xv = __ldg((const float4*)&x[(size_t)ts[pp] * 1024 + tid * 4]);
                float vv[4] = {xv.x, xv.y, xv.z, xv.w};
                #pragma unroll
                for (int q = 0; q < 4; q++) {
                    __nv_bfloat16 h, l;
                    split_bf16(vv[q], h, l);
                    sXT[pp][j0 + q][i]      = h;
                    sXT[pp][j0 + q][36 + i] = l;
                }
            }
        }
        __syncthreads();

        // ---- T phase: D[64,32] over 6 k-steps ----
        {
            float d[4][4];
            #pragma unroll
            for (int nt = 0; nt < 4; nt++)
                #pragma unroll
                for (int q = 0; q < 4; q++) d[nt][q] = 0.f;
            #pragma unroll
            for (int s = 0; s < 6; s++) {
                unsigned a[4];
                int ac = AOFF[s] + 2 * tig;
                a[0] = *(const unsigned*)&sA[R + gid][ac];
                a[1] = *(const unsigned*)&sA[R + gid + 8][ac];
                a[2] = *(const unsigned*)&sA[R + gid][ac + 8];
                a[3] = *(const unsigned*)&sA[R + gid + 8][ac + 8];
                int bc = BOFF[s] + 2 * tig;
                #pragma unroll
                for (int nt = 0; nt < 4; nt++) {
                    unsigned bf[2];
                    bf[0] = *(const unsigned*)&sXT[pl][nt * 8 + gid][bc];
                    bf[1] = *(const unsigned*)&sXT[pl][nt * 8 + gid][bc + 8];
                    mma_bf16(d[nt], a, bf);
                }
            }
            // store T hi/lo
            #pragma unroll
            for (int nt = 0; nt < 4; nt++) {
                int col = nt * 8 + 2 * tig;
                __nv_bfloat16 h0, l0, h1, l1;
                split_bf16(d[nt][0], h0, l0);
                split_bf16(d[nt][1], h1, l1);
                *(__nv_bfloat162*)&sT[pl][R + gid][col]      = __halves2bfloat162(h0, h1);
                *(__nv_bfloat162*)&sT[pl][R + gid][col + 36] = __halves2bfloat162(l0, l1);
                split_bf16(d[nt][2], h0, l0);
                split_bf16(d[nt][3], h1, l1);
                *(__nv_bfloat162*)&sT[pl][R + gid + 8][col]      = __halves2bfloat162(h0, h1);
                *(__nv_bfloat162*)&sT[pl][R + gid + 8][col + 36] = __halves2bfloat162(l0, l1);
            }
        }
        __syncthreads();

        // ---- Y phase: D[64,64] over 6 k-steps ----
        {
            float y[8][4];
            #pragma unroll
            for (int nt = 0; nt < 8; nt++)
                #pragma unroll
                for (int q = 0; q < 4; q++) y[nt][q] = 0.f;
            #pragma unroll
            for (int s = 0; s < 6; s++) {
                unsigned a[4];
                int ac = AOFF[s] + 2 * tig;
                a[0] = *(const unsigned*)&sT[pl][R + gid][ac];
                a[1] = *(const unsigned*)&sT[pl][R + gid + 8][ac];
                a[2] = *(const unsigned*)&sT[pl][R + gid][ac + 8];
                a[3] = *(const unsigned*)&sT[pl][R + gid + 8][ac + 8];
                int bc = BOFF[s] + 2 * tig;
                #pragma unroll
                for (int nt = 0; nt < 8; nt++) {
                    unsigned bf[2];
                    bf[0] = *(const unsigned*)&sB[nt * 8 + gid][bc];
                    bf[1] = *(const unsigned*)&sB[nt * 8 + gid][bc + 8];
                    mma_bf16(y[nt], a, bf);
                }
            }
            if (myValid) {
                float* yo = &g_yup[(size_t)myPair * 4096];
                #pragma unroll
                for (int nt = 0; nt < 8; nt++) {
                    int col = nt * 8 + 2 * tig;
                    *(float2*)&yo[(R + gid) * 64 + col]     = make_float2(y[nt][0], y[nt][1]);
                    *(float2*)&yo[(R + gid + 8) * 64 + col] = make_float2(y[nt][2], y[nt][3]);
                }
            }
        }
        __syncthreads();
    }
}

// ---------------------------------------------------------------------------
// Down bilinear, tensor-core version.
// Per pair: T(32x64) = A(32x64) H(64x64), Y(32x32) = T B^T.
// Pitch 136 bf16 (= 68 words == 4 mod 32). 1 pair per iteration, 8 warps.
// ---------------------------------------------------------------------------
__global__ __launch_bounds__(256) void bilinear_down(
    const float* __restrict__ A, const float* __restrict__ B)
{
    const int b = blockIdx.x;
    if (b >= g_nchunks) return;
    const int2 ch   = g_chunk[b];
    const int e     = ch.x;
    const int start = ch.y;
    const int cnt   = g_cnt[e];
    const int tid   = threadIdx.x;
    const int lane  = tid & 31;
    const int warp  = tid >> 5;
    const int gid   = lane >> 2;
    const int tig   = lane & 3;

    __shared__ __align__(16) __nv_bfloat16 sA[32][136];   // A-op: [o][ihi 0-63 | ilo 68-131]
    __shared__ __align__(16) __nv_bfloat16 sB[32][136];   // B-op: [p][jhi | jlo]
    __shared__ __align__(16) __nv_bfloat16 sHT[64][136];  // B-op: [j][ihi | ilo]  (H^T)
    __shared__ __align__(16) __nv_bfloat16 sT[32][136];   // A-op: [o][jhi | jlo]

    // stage A_down[e] (32x64), B_down[e] (32x64) hi/lo
    {
        const float4* a4 = (const float4*)(A + (size_t)e * 2048);
        const float4* b4 = (const float4*)(B + (size_t)e * 2048);
        #pragma unroll
        for (int rr = 0; rr < 2; rr++) {
            int f = tid + 256 * rr;
            int row = f >> 4, c0 = (f & 15) * 4;
            float4 av = __ldg(&a4[f]);
            float4 bv = __ldg(&b4[f]);
            float aa[4] = {av.x, av.y, av.z, av.w};
            float bb[4] = {bv.x, bv.y, bv.z, bv.w};
            #pragma unroll
            for (int q = 0; q < 4; q++) {
                __nv_bfloat16 h, l;
                split_bf16(aa[q], h, l);
                sA[row][c0 + q] = h; sA[row][68 + c0 + q] = l;
                split_bf16(bb[q], h, l);
                sB[row][c0 + q] = h; sB[row][68 + c0 + q] = l;
            }
        }
    }

    // 12 k-steps: (hi,hi)x4, (lo,hi)x4, (hi,lo)x4   (element offsets)
    const int AOFF[12] = {0,16,32,48, 68,84,100,116, 0,16,32,48};
    const int BOFF[12] = {0,16,32,48, 0,16,32,48, 68,84,100,116};

    for (int u = 0; u < TPB; u++) {
        int pi = start + u;
        if (pi >= cnt) break;
        int pair = g_list[e * NPAIR + pi];
        int t    = pair >> 1;

        // ---- stage H^T hi/lo ----
        {
            const float4* h4 = (const float4*)&g_h[(size_t)t * 4096];
            #pragma unroll
            for (int rr = 0; rr < 4; rr++) {
                int f = tid + 256 * rr;
                int i = f >> 4, j0 = (f & 15) * 4;
                float4 hv = __ldg(&h4[f]);
                float vv[4] = {hv.x, hv.y, hv.z, hv.w};
                #pragma unroll
                for (int q = 0; q < 4; q++) {
                    __nv_bfloat16 h, l;
                    split_bf16(vv[q], h, l);
                    sHT[j0 + q][i]      = h;
                    sHT[j0 + q][68 + i] = l;
                }
            }
        }
        __syncthreads();

        // ---- T phase: M=32 (mt=warp&1), N=64: warp takes 2 n-tiles ----
        {
            const int mt  = warp & 1;
            const int ntb = (warp >> 1) * 2;
            const int R   = mt * 16;
            float d[2][4];
            #pragma unroll
            for (int nn = 0; nn < 2; nn++)
                #pragma unroll
                for (int q = 0; q < 4; q++) d[nn][q] = 0.f;
            #pragma unroll
            for (int s = 0; s < 12; s++) {
                unsigned a[4];
                int ac = AOFF[s] + 2 * tig;
                a[0] = *(const unsigned*)&sA[R + gid][ac];
                a[1] = *(const unsigned*)&sA[R + gid + 8][ac];
                a[2] = *(const unsigned*)&sA[R + gid][ac + 8];
                a[3] = *(const unsigned*)&sA[R + gid + 8][ac + 8];
                int bc = BOFF[s] + 2 * tig;
                #pragma unroll
                for (int nn = 0; nn < 2; nn++) {
                    unsigned bf[2];
                    bf[0] = *(const unsigned*)&sHT[(ntb + nn) * 8 + gid][bc];
                    bf[1] = *(const unsigned*)&sHT[(ntb + nn) * 8 + gid][bc + 8];
                    mma_bf16(d[nn], a, bf);
                }
            }
            #pragma unroll
            for (int nn = 0; nn < 2; nn++) {
                int col = (ntb + nn) * 8 + 2 * tig;
                __nv_bfloat16 h0, l0, h1, l1;
                split_bf16(d[nn][0], h0, l0);
                split_bf16(d[nn][1], h1, l1);
                *(__nv_bfloat162*)&sT[R + gid][col]      = __halves2bfloat162(h0, h1);
                *(__nv_bfloat162*)&sT[R + gid][col + 68] = __halves2bfloat162(l0, l1);
                split_bf16(d[nn][2], h0, l0);
                split_bf16(d[nn][3], h1, l1);
                *(__nv_bfloat162*)&sT[R + gid + 8][col]      = __halves2bfloat162(h0, h1);
                *(__nv_bfloat162*)&sT[R + gid + 8][col + 68] = __halves2bfloat162(l0, l1);
            }
        }
        __syncthreads();

        // ---- Y phase: M=32, N=32: warp takes 1 tile (mt=warp&1, nt=warp>>1) ----
        {
            const int mt = warp & 1;
            const int nt = warp >> 1;
            const int R  = mt * 16;
            float y[4] = {0.f, 0.f, 0.f, 0.f};
            #pragma unroll
            for (int s = 0; s < 12; s++) {
                unsigned a[4];
                int ac = AOFF[s] + 2 * tig;
                a[0] = *(const unsigned*)&sT[R + gid][ac];
                a[1] = *(const unsigned*)&sT[R + gid + 8][ac];
                a[2] = *(const unsigned*)&sT[R + gid][ac + 8];
                a[3] = *(const unsigned*)&sT[R + gid + 8][ac + 8];
                int bc = BOFF[s] + 2 * tig;
                unsigned bf[2];
                bf[0] = *(const unsigned*)&sB[nt * 8 + gid][bc];
                bf[1] = *(const unsigned*)&sB[nt * 8 + gid][bc + 8];
                mma_bf16(y, a, bf);
            }
            float* yo = &g_ydown[(size_t)pair * 1024];
            int col = nt * 8 + 2 * tig;
            *(float2*)&yo[(R + gid) * 32 + col]     = make_float2(y[0], y[1]);
            *(float2*)&yo[(R + gid + 8) * 32 + col] = make_float2(y[2], y[3]);
        }
        __syncthreads();
    }
}

// ---------------------------------------------------------------------------
// Combine kernels (unchanged)
// ---------------------------------------------------------------------------
__global__ __launch_bounds__(256) void combine_up(
    const float* __restrict__ scale, const float* __restrict__ bias)
{
    const int t   = blockIdx.x;
    const int tid = threadIdx.x;
    const float p0 = g_prob[2 * t], p1 = g_prob[2 * t + 1];
    const float s  = __ldg(scale);
    const float4* y0 = (const float4*)&g_yup[(size_t)(2 * t) * 4096];
    const float4* y1 = (const float4*)&g_yup[(size_t)(2 * t + 1) * 4096];
    const float4* b4 = (const float4*)bias;
    float4* h4 = (float4*)&g_h[(size_t)t * 4096];
    #pragma unroll
    for (int rr = 0; rr < 4; rr++) {
        int f = tid + 256 * rr;
        float4 a = __ldg(&y0[f]), c = __ldg(&y1[f]), bb = __ldg(&b4[f]);
        float4 v;
        v.x = gelu_erf(s * (p0 * a.x + p1 * c.x) + bb.x);
        v.y = gelu_erf(s * (p0 * a.y + p1 * c.y) + bb.y);
        v.z = gelu_erf(s * (p0 * a.z + p1 * c.z) + bb.z);
        v.w = gelu_erf(s * (p0 * a.w + p1 * c.w) + bb.w);
        h4[f] = v;
    }
}

__global__ __launch_bounds__(256) void combine_down(
    const float* __restrict__ scale, const float* __restrict__ bias,
    float* __restrict__ out)
{
    const int t   = blockIdx.x;
    const int tid = threadIdx.x;
    const float p0 = g_prob[2 * t], p1 = g_prob[2 * t + 1];
    const float s  = __ldg(scale);
    const float4* y0 = (const float4*)&g_ydown[(size_t)(2 * t) * 1024];
    const float4* y1 = (const float4*)&g_ydown[(size_t)(2 * t + 1) * 1024];
    const float4* b4 = (const float4*)bias;
    float4 a = __ldg(&y0[tid]), c = __ldg(&y1[tid]), bb = __ldg(&b4[tid]);
    float4 v;
    v.x = s * (p0 * a.x + p1 * c.x) + bb.x;
    v.y = s * (p0 * a.y + p1 * c.y) + bb.y;
    v.z = s * (p0 * a.z + p1 * c.z) + bb.z;
    v.w = s * (p0 * a.w + p1 * c.w) + bb.w;
    ((float4*)&out[(size_t)t * 1024])[tid] = v;
}

// ---------------------------------------------------------------------------
extern "C" void kernel_launch(void* const* d_in, const int* in_sizes, int n_in,
                              void* d_out, int out_size)
{
    const float* x          = (const float*)d_in[0];
    const float* W_up       = (const float*)d_in[1];
    const float* A_up       = (const float*)d_in[2];
    const float* B_up       = (const float*)d_in[3];
    const float* scale_up   = (const float*)d_in[4];
    const float* bias_up    = (const float*)d_in[5];
    const float* W_down     = (const float*)d_in[6];
    const float* A_down     = (const float*)d_in[7];
    const float* B_down     = (const float*)d_in[8];
    const float* scale_down = (const float*)d_in[9];
    const float* bias_down  = (const float*)d_in[10];
    float*       out        = (float*)d_out;

    const int n_tok = in_sizes[0] / 1024;     // 8192

    float *h_ptr = nullptr, *lg1 = nullptr, *lg2 = nullptr;
    cudaGetSymbolAddress((void**)&h_ptr, g_h);
    cudaGetSymbolAddress((void**)&lg1, g_logits);
    cudaGetSymbolAddress((void**)&lg2, g_logits2);

    // ---- up ----
    router_gemm<1024, 1><<<n_tok / 64, 256>>>(x, W_up, lg1, nullptr, 1024);
    top2_kernel<<<n_tok / 8, 256>>>(lg1, nullptr);
    prefix_kernel<<<1, 64>>>();
    bilinear_up<<<MAXCHUNK, 256>>>(x, A_up, B_up);
    combine_up<<<n_tok, 256>>>(scale_up, bias_up);

    // ---- down (K split in 2 within one 256-block launch) ----
    router_gemm<2048, 2><<<2 * (n_tok / 64), 256>>>(h_ptr, W_down, lg1, lg2, 4096);
    top2_kernel<<<n_tok / 8, 256>>>(lg1, lg2);
    prefix_kernel<<<1, 64>>>();
    bilinear_down<<<MAXCHUNK, 256>>>(A_down, B_down);
    combine_down<<<n_tok, 256>>>(scale_down, bias_down, out);
}